// round 7
// baseline (speedup 1.0000x reference)
#include <cuda_runtime.h>
#include <cuda_fp16.h>
#include <cstdint>

#define F   16384
#define D   768
#define BSZ 512      // B*S
#define C   16
#define M   (F*C)

#define TI  64       // feature tile in scatter
#define TBS 128      // batch-seq tile in scatter

// Scratch (device globals — no allocations allowed)
__device__ __half g_udec_h[(size_t)F * D];     // up_decoder transposed, fp16: [F, D]
__device__ __half g_ufacts_h[(size_t)F * BSZ]; // up_facts transposed, fp16:   [F, BS]
__device__ float  g_values[M];

// ---------------------------------------------------------------------------
// Persistent pipelined transpose+convert (parameterized, cols fixed = F).
// src [rows, F] -> dst [F, rows]. Double-buffered smem, one barrier/tile,
// next tile's LDGs issued before current tile's convert/store phase.
// ntiles = (rows/32) * 512 ; tile decode: ty = t>>9, tx = t&511.
// ---------------------------------------------------------------------------
__global__ __launch_bounds__(256) void k_tpipe(const float* __restrict__ src,
                                               __half* __restrict__ dst,
                                               int rows, int ntiles) {
    __shared__ float buf[2][32][33];
    int lx = threadIdx.x, ly = threadIdx.y;

    int tt = blockIdx.x;
    if (tt >= ntiles) return;

    int ty = tt >> 9, tx = tt & 511;
    float v[4];
#pragma unroll
    for (int k = 0; k < 4; k++)
        v[k] = src[(size_t)(ty * 32 + ly + 8 * k) * F + tx * 32 + lx];

    int p = 0;
    while (true) {
#pragma unroll
        for (int k = 0; k < 4; k++)
            buf[p][ly + 8 * k][lx] = v[k];

        int tn = tt + gridDim.x;
        __syncthreads();

        bool have = (tn < ntiles);
        int ty2 = tn >> 9, tx2 = tn & 511;
        float nv[4];
        if (have) {
#pragma unroll
            for (int k = 0; k < 4; k++)
                nv[k] = src[(size_t)(ty2 * 32 + ly + 8 * k) * F + tx2 * 32 + lx];
        }

#pragma unroll
        for (int k = 0; k < 4; k++)
            dst[(size_t)(tx * 32 + ly + 8 * k) * rows + ty * 32 + lx] =
                __float2half_rn(buf[p][lx][ly + 8 * k]);

        if (!have) break;
        p ^= 1;
        tt = tn; tx = tx2; ty = ty2;
#pragma unroll
        for (int k = 0; k < 4; k++) v[k] = nv[k];
    }
}

// ---------------------------------------------------------------------------
// values[i*C+c] = down_encoder[i,:] . udec_h[j_ic,:]
// One warp per feature i, single-wave grid-stride. (At L2 cap — unchanged.)
// ---------------------------------------------------------------------------
__global__ __launch_bounds__(256, 2) void k_values(const float* __restrict__ down_enc,
                                                   const int* __restrict__ j_idx) {
    int warp = threadIdx.x >> 5, lane = threadIdx.x & 31;
    int gw = blockIdx.x * 8 + warp;
    int nw = gridDim.x * 8;

    for (int i = gw; i < F; i += nw) {
        const float4* dr = reinterpret_cast<const float4*>(down_enc + (size_t)i * D);
        float4 dA[3], dB[3];
#pragma unroll
        for (int t = 0; t < 3; t++) {
            dA[t] = dr[t * 64 + lane * 2];
            dB[t] = dr[t * 64 + lane * 2 + 1];
        }
        int jl = 0;
        if (lane < C) jl = j_idx[i * C + lane];

        float acc[C];
#pragma unroll
        for (int c = 0; c < C; c++) acc[c] = 0.f;

#pragma unroll
        for (int g = 0; g < C; g += 4) {
            uint4 u[4][3];
#pragma unroll
            for (int q = 0; q < 4; q++) {
                int j = __shfl_sync(0xffffffffu, jl, g + q);
                const uint4* ur = reinterpret_cast<const uint4*>(g_udec_h + (size_t)j * D);
#pragma unroll
                for (int t = 0; t < 3; t++) u[q][t] = ur[t * 32 + lane];
            }
#pragma unroll
            for (int q = 0; q < 4; q++) {
                float a = acc[g + q];
#pragma unroll
                for (int t = 0; t < 3; t++) {
                    float2 f;
                    f = __half22float2(*reinterpret_cast<__half2*>(&u[q][t].x));
                    a = fmaf(f.x, dA[t].x, fmaf(f.y, dA[t].y, a));
                    f = __half22float2(*reinterpret_cast<__half2*>(&u[q][t].y));
                    a = fmaf(f.x, dA[t].z, fmaf(f.y, dA[t].w, a));
                    f = __half22float2(*reinterpret_cast<__half2*>(&u[q][t].z));
                    a = fmaf(f.x, dB[t].x, fmaf(f.y, dB[t].y, a));
                    f = __half22float2(*reinterpret_cast<__half2*>(&u[q][t].w));
                    a = fmaf(f.x, dB[t].z, fmaf(f.y, dB[t].w, a));
                }
                acc[g + q] = a;
            }
        }
#pragma unroll
        for (int c = 0; c < C; c++) {
#pragma unroll
            for (int o = 16; o; o >>= 1)
                acc[c] += __shfl_xor_sync(0xffffffffu, acc[c], o);
        }
#pragma unroll
        for (int c = 0; c < C; c++)
            if (lane == c) g_values[i * C + c] = acc[c];
    }
}

// ---------------------------------------------------------------------------
// Scatter: out[bs, i] = sum_c values[i*C+c] * ufacts_h[j[i*C+c], bs]
// (Near L2 cap — unchanged.)
// ---------------------------------------------------------------------------
__global__ __launch_bounds__(256) void k_scatter(const int* __restrict__ j_idx,
                                                 float* __restrict__ out) {
    __shared__ float sacc[TI][TBS + 1];
    __shared__ float sval[TI * C];
    __shared__ int   sj[TI * C];

    int i0  = blockIdx.x * TI;
    int bs0 = blockIdx.y * TBS;
    int tid = threadIdx.x;

    for (int idx = tid; idx < TI * C; idx += 256) {
        sval[idx] = g_values[i0 * C + idx];
        sj[idx]   = j_idx[i0 * C + idx];
    }
    __syncthreads();

    int warp = tid >> 5, lane = tid & 31;
#pragma unroll 1
    for (int ii = warp * 8; ii < warp * 8 + 8; ii++) {
        float a0 = 0.f, a1 = 0.f, a2 = 0.f, a3 = 0.f;
#pragma unroll
        for (int c = 0; c < C; c++) {
            int   j = sj[ii * C + c];
            float v = sval[ii * C + c];
            uint2 u = *reinterpret_cast<const uint2*>(
                          g_ufacts_h + (size_t)j * BSZ + bs0 + lane * 4);
            float2 f;
            f = __half22float2(*reinterpret_cast<__half2*>(&u.x));
            a0 = fmaf(v, f.x, a0); a1 = fmaf(v, f.y, a1);
            f = __half22float2(*reinterpret_cast<__half2*>(&u.y));
            a2 = fmaf(v, f.x, a2); a3 = fmaf(v, f.y, a3);
        }
        sacc[ii][lane * 4 + 0] = a0;
        sacc[ii][lane * 4 + 1] = a1;
        sacc[ii][lane * 4 + 2] = a2;
        sacc[ii][lane * 4 + 3] = a3;
    }
    __syncthreads();

    for (int idx = tid; idx < TI * TBS; idx += 256) {
        int bs = idx >> 6;          // / TI
        int ii = idx & (TI - 1);
        out[(size_t)(bs0 + bs) * F + i0 + ii] = sacc[ii][bs];
    }
}

// ---------------------------------------------------------------------------
// Side stream + events, created once at library load (no device memory).
// ---------------------------------------------------------------------------
namespace {
struct SideStream {
    cudaStream_t s2;
    cudaEvent_t  evFork, evJoin;
    SideStream() {
        cudaStreamCreateWithFlags(&s2, cudaStreamNonBlocking);
        cudaEventCreateWithFlags(&evFork, cudaEventDisableTiming);
        cudaEventCreateWithFlags(&evJoin, cudaEventDisableTiming);
    }
};
SideStream g_ss;
}

extern "C" void kernel_launch(void* const* d_in, const int* in_sizes, int n_in,
                              void* d_out, int out_size) {
    const float* up_facts = (const float*)d_in[0];  // [B,S,F]
    const float* down_enc = (const float*)d_in[1];  // [F, D]
    const float* up_dec   = (const float*)d_in[2];  // [D, F]
    const int*   j_idx    = (const int*)d_in[4];    // [M]
    float* out = (float*)d_out;                     // [B,S,F]

    void* p;
    cudaGetSymbolAddress(&p, g_udec_h);
    __half* udecH = (__half*)p;
    cudaGetSymbolAddress(&p, g_ufacts_h);
    __half* ufactsH = (__half*)p;

    dim3 tb(32, 8);

    // Main stream: up_decoder transpose (k_values' only dependency)
    k_tpipe<<<1184, tb>>>(up_dec, udecH, D, (D / 32) * 512);

    // Fork: up_facts transpose runs concurrently with k_values
    cudaEventRecord(g_ss.evFork, 0);
    cudaStreamWaitEvent(g_ss.s2, g_ss.evFork, 0);
    k_tpipe<<<592, tb, 0, g_ss.s2>>>(up_facts, ufactsH, BSZ, (BSZ / 32) * 512);
    cudaEventRecord(g_ss.evJoin, g_ss.s2);

    // Main stream: values (needs udec_h only)
    k_values<<<296, 256>>>(down_enc, j_idx);

    // Join, then scatter (needs ufacts_h + values)
    cudaStreamWaitEvent(0, g_ss.evJoin, 0);
    k_scatter<<<dim3(F / TI, BSZ / TBS), 256>>>(j_idx, out);
}

// round 8
// speedup vs baseline: 1.0021x; 1.0021x over previous
#include <cuda_runtime.h>
#include <cuda_fp16.h>
#include <cstdint>

#define F   16384
#define D   768
#define BSZ 512      // B*S
#define C   16
#define M   (F*C)

#define TI  64       // feature tile in scatter
#define TBS 128      // batch-seq tile in scatter

// Scratch (device globals — no allocations allowed)
__device__ __half g_udec_h[(size_t)F * D];     // up_decoder transposed, fp16: [F, D]
__device__ __half g_ufacts_h[(size_t)F * BSZ]; // up_facts transposed, fp16:   [F, BS]
__device__ float  g_values[M];

// ---------------------------------------------------------------------------
// Persistent pipelined transpose+convert (R6 kernel — measured near the
// mixed-read/write DRAM ceiling; leave alone).
//   tiles [0, 12288):    up_decoder [D, F]   -> g_udec_h   [F, D]
//   tiles [12288, 20480): up_facts  [BSZ, F] -> g_ufacts_h [F, BSZ]
// ---------------------------------------------------------------------------
#define T_UDEC_TILES 12288   // (D/32) * (F/32)
#define T_TOT_TILES  20480
#define T_GRID       1184    // 8 blocks/SM * 148

struct TileMeta {
    const float* src;
    __half*      dst;
    int rows, cols, tx, ty;
};

__device__ __forceinline__ TileMeta decode_tile(int tt, const float* up_dec,
                                                const float* up_facts) {
    TileMeta m;
    if (tt < T_UDEC_TILES) {
        m.src = up_dec;   m.dst = g_udec_h;   m.rows = D;   m.cols = F;
        m.ty = tt >> 9;   m.tx = tt & 511;
    } else {
        int t2 = tt - T_UDEC_TILES;
        m.src = up_facts; m.dst = g_ufacts_h; m.rows = BSZ; m.cols = F;
        m.ty = t2 >> 9;   m.tx = t2 & 511;
    }
    return m;
}

__global__ __launch_bounds__(256) void k_transpose_pipe(
        const float* __restrict__ up_dec, const float* __restrict__ up_facts) {
    __shared__ float buf[2][32][33];
    int lx = threadIdx.x, ly = threadIdx.y;

    int tt = blockIdx.x;
    if (tt >= T_TOT_TILES) return;

    TileMeta cur = decode_tile(tt, up_dec, up_facts);
    float v[4];
#pragma unroll
    for (int k = 0; k < 4; k++)
        v[k] = cur.src[(size_t)(cur.ty * 32 + ly + 8 * k) * cur.cols + cur.tx * 32 + lx];

    int p = 0;
    while (true) {
#pragma unroll
        for (int k = 0; k < 4; k++)
            buf[p][ly + 8 * k][lx] = v[k];

        int tn = tt + T_GRID;
        __syncthreads();

        TileMeta nxt;
        float nv[4];
        bool have = (tn < T_TOT_TILES);
        if (have) {
            nxt = decode_tile(tn, up_dec, up_facts);
#pragma unroll
            for (int k = 0; k < 4; k++)
                nv[k] = nxt.src[(size_t)(nxt.ty * 32 + ly + 8 * k) * nxt.cols + nxt.tx * 32 + lx];
        }

#pragma unroll
        for (int k = 0; k < 4; k++)
            cur.dst[(size_t)(cur.tx * 32 + ly + 8 * k) * cur.rows + cur.ty * 32 + lx] =
                __float2half_rn(buf[p][lx][ly + 8 * k]);

        if (!have) break;
        p ^= 1;
        tt = tn;
        cur = nxt;
#pragma unroll
        for (int k = 0; k < 4; k++) v[k] = nv[k];
    }
}

// ---------------------------------------------------------------------------
// values[i*C+c] = down_encoder[i,:] . udec_h[j_ic,:]
// One warp per feature i, single-wave grid-stride. (At LTS cap — unchanged.)
// ---------------------------------------------------------------------------
__global__ __launch_bounds__(256, 2) void k_values(const float* __restrict__ down_enc,
                                                   const int* __restrict__ j_idx) {
    int warp = threadIdx.x >> 5, lane = threadIdx.x & 31;
    int gw = blockIdx.x * 8 + warp;
    int nw = gridDim.x * 8;

    for (int i = gw; i < F; i += nw) {
        const float4* dr = reinterpret_cast<const float4*>(down_enc + (size_t)i * D);
        float4 dA[3], dB[3];
#pragma unroll
        for (int t = 0; t < 3; t++) {
            dA[t] = dr[t * 64 + lane * 2];
            dB[t] = dr[t * 64 + lane * 2 + 1];
        }
        int jl = 0;
        if (lane < C) jl = j_idx[i * C + lane];

        float acc[C];
#pragma unroll
        for (int c = 0; c < C; c++) acc[c] = 0.f;

#pragma unroll
        for (int g = 0; g < C; g += 4) {
            uint4 u[4][3];
#pragma unroll
            for (int q = 0; q < 4; q++) {
                int j = __shfl_sync(0xffffffffu, jl, g + q);
                const uint4* ur = reinterpret_cast<const uint4*>(g_udec_h + (size_t)j * D);
#pragma unroll
                for (int t = 0; t < 3; t++) u[q][t] = ur[t * 32 + lane];
            }
#pragma unroll
            for (int q = 0; q < 4; q++) {
                float a = acc[g + q];
#pragma unroll
                for (int t = 0; t < 3; t++) {
                    float2 f;
                    f = __half22float2(*reinterpret_cast<__half2*>(&u[q][t].x));
                    a = fmaf(f.x, dA[t].x, fmaf(f.y, dA[t].y, a));
                    f = __half22float2(*reinterpret_cast<__half2*>(&u[q][t].y));
                    a = fmaf(f.x, dA[t].z, fmaf(f.y, dA[t].w, a));
                    f = __half22float2(*reinterpret_cast<__half2*>(&u[q][t].z));
                    a = fmaf(f.x, dB[t].x, fmaf(f.y, dB[t].y, a));
                    f = __half22float2(*reinterpret_cast<__half2*>(&u[q][t].w));
                    a = fmaf(f.x, dB[t].z, fmaf(f.y, dB[t].w, a));
                }
                acc[g + q] = a;
            }
        }
#pragma unroll
        for (int c = 0; c < C; c++) {
#pragma unroll
            for (int o = 16; o; o >>= 1)
                acc[c] += __shfl_xor_sync(0xffffffffu, acc[c], o);
        }
#pragma unroll
        for (int c = 0; c < C; c++)
            if (lane == c) g_values[i * C + c] = acc[c];
    }
}

// ---------------------------------------------------------------------------
// Scatter: out[bs, i] = sum_c values[i*C+c] * ufacts_h[j[i*C+c], bs]
// fp16 staging tile packed as half2 words, row stride 65 uints:
//   read-phase bank = (65*ii + bs/2) mod 32 = (ii + const) mod 32 -> conflict-free.
// Smem 41KB -> 24.6KB => occupancy ~5 blocks/SM (was limited to fewer).
// ---------------------------------------------------------------------------
#define SACC_W 65   // uints per row (= 130 halfs, only 128 used)

__global__ __launch_bounds__(256) void k_scatter(const int* __restrict__ j_idx,
                                                 float* __restrict__ out) {
    __shared__ unsigned int sacc[TI][SACC_W];
    __shared__ float sval[TI * C];
    __shared__ int   sj[TI * C];

    int i0  = blockIdx.x * TI;
    int bs0 = blockIdx.y * TBS;
    int tid = threadIdx.x;

    for (int idx = tid; idx < TI * C; idx += 256) {
        sval[idx] = g_values[i0 * C + idx];
        sj[idx]   = j_idx[i0 * C + idx];
    }
    __syncthreads();

    int warp = tid >> 5, lane = tid & 31;
#pragma unroll 1
    for (int ii = warp * 8; ii < warp * 8 + 8; ii++) {
        float a0 = 0.f, a1 = 0.f, a2 = 0.f, a3 = 0.f;
#pragma unroll
        for (int c = 0; c < C; c++) {
            int   j = sj[ii * C + c];
            float v = sval[ii * C + c];
            uint2 u = *reinterpret_cast<const uint2*>(
                          g_ufacts_h + (size_t)j * BSZ + bs0 + lane * 4);
            float2 f;
            f = __half22float2(*reinterpret_cast<__half2*>(&u.x));
            a0 = fmaf(v, f.x, a0); a1 = fmaf(v, f.y, a1);
            f = __half22float2(*reinterpret_cast<__half2*>(&u.y));
            a2 = fmaf(v, f.x, a2); a3 = fmaf(v, f.y, a3);
        }
        __half2 p0 = __floats2half2_rn(a0, a1);
        __half2 p1 = __floats2half2_rn(a2, a3);
        sacc[ii][lane * 2 + 0] = *reinterpret_cast<unsigned int*>(&p0);
        sacc[ii][lane * 2 + 1] = *reinterpret_cast<unsigned int*>(&p1);
    }
    __syncthreads();

    // Coalesced stores: consecutive tid -> consecutive feature i
    for (int idx = tid; idx < TI * TBS; idx += 256) {
        int bs = idx >> 6;          // 0..127
        int ii = idx & (TI - 1);    // 0..63
        unsigned int w = sacc[ii][bs >> 1];
        __half2 h2 = *reinterpret_cast<__half2*>(&w);
        float v = __half2float((bs & 1) ? __high2half(h2) : __low2half(h2));
        out[(size_t)(bs0 + bs) * F + i0 + ii] = v;
    }
}

// ---------------------------------------------------------------------------
extern "C" void kernel_launch(void* const* d_in, const int* in_sizes, int n_in,
                              void* d_out, int out_size) {
    const float* up_facts = (const float*)d_in[0];  // [B,S,F]
    const float* down_enc = (const float*)d_in[1];  // [F, D]
    const float* up_dec   = (const float*)d_in[2];  // [D, F]
    const int*   j_idx    = (const int*)d_in[4];    // [M]
    float* out = (float*)d_out;                     // [B,S,F]

    dim3 tb(32, 8);
    k_transpose_pipe<<<T_GRID, tb>>>(up_dec, up_facts);
    k_values<<<296, 256>>>(down_enc, j_idx);
    k_scatter<<<dim3(F / TI, BSZ / TBS), 256>>>(j_idx, out);
}